// round 3
// baseline (speedup 1.0000x reference)
#include <cuda_runtime.h>

// ConceptGaussians gather:
//   means[b, d]    = mean[d, labels[b, d]]
//   log_vars[b, d] = log_var[d, labels[b, d]]
// labels: [B, 8] int32, mean/log_var: [8, 64] f32.
// Output layout: means (B*8 floats) followed by log_vars (B*8 floats).

#define N_DOMAINS 8
#define MAX_CONCEPTS 64
#define TBL_ELEMS (N_DOMAINS * MAX_CONCEPTS)   // 512

__global__ void __launch_bounds__(256)
concept_gather_kernel(const int4* __restrict__ labels4,
                      const float* __restrict__ mean,
                      const float* __restrict__ log_var,
                      float4* __restrict__ out_mean4,
                      float4* __restrict__ out_lv4,
                      int n4)
{
    // Stage both tables interleaved: one float2 lookup yields (mean, log_var).
    __shared__ float2 tbl[TBL_ELEMS];
    for (int k = threadIdx.x; k < TBL_ELEMS; k += blockDim.x) {
        tbl[k] = make_float2(mean[k], log_var[k]);
    }
    __syncthreads();

    int i = blockIdx.x * blockDim.x + threadIdx.x;
    if (i >= n4) return;

    int4 L = labels4[i];
    // element index of first label = 4*i; domain stride pattern repeats every 8.
    // 4*i % 8 is 0 or 4, so the four domains are dbase, dbase+1, dbase+2, dbase+3.
    int dbase = (i << 2) & (N_DOMAINS - 1);
    const float2* row = tbl + dbase * MAX_CONCEPTS;

    float2 a = row[ 0 * MAX_CONCEPTS + (L.x & (MAX_CONCEPTS - 1))];
    float2 b = row[ 1 * MAX_CONCEPTS + (L.y & (MAX_CONCEPTS - 1))];
    float2 c = row[ 2 * MAX_CONCEPTS + (L.z & (MAX_CONCEPTS - 1))];
    float2 d = row[ 3 * MAX_CONCEPTS + (L.w & (MAX_CONCEPTS - 1))];

    out_mean4[i] = make_float4(a.x, b.x, c.x, d.x);
    out_lv4[i]   = make_float4(a.y, b.y, c.y, d.y);
}

extern "C" void kernel_launch(void* const* d_in, const int* in_sizes, int n_in,
                              void* d_out, int out_size)
{
    const int*   labels  = (const int*)  d_in[0];   // [B, 8] int32
    const float* mean    = (const float*)d_in[1];   // [8, 64]
    const float* log_var = (const float*)d_in[2];   // [8, 64]

    int n_elems = in_sizes[0];          // B * 8
    int n4      = n_elems >> 2;         // int4 chunks

    float* out       = (float*)d_out;
    float* out_mean  = out;             // first half: means
    float* out_lv    = out + n_elems;   // second half: log_vars

    const int threads = 256;
    int blocks = (n4 + threads - 1) / threads;

    concept_gather_kernel<<<blocks, threads>>>(
        (const int4*)labels, mean, log_var,
        (float4*)out_mean, (float4*)out_lv, n4);
}